// round 13
// baseline (speedup 1.0000x reference)
#include <cuda_runtime.h>

#define NN 50000
#define EE 800000
#define NEG 0.2f

// ---------------- scratch (device globals) ----------------------------------
__device__ __align__(16) int   g_csrc[EE];      // CSR: src ids grouped by dst
__device__ __align__(16) int   g_deg[NN];        // zero-init; re-zeroed by scatter
__device__ int   g_off[NN + 1];
__device__ int   g_cursor[NN];
__device__ __align__(16) float g_h[NN * 64];
__device__ __align__(16) float g_featA[NN * 64];
__device__ __align__(16) float g_featB[NN * 64];
__device__ __align__(16) float g_as[NN * 4];
__device__ __align__(16) float g_ad[NN * 4];

__device__ __forceinline__ float lrelu(float x) { return x > 0.f ? x : NEG * x; }

// int64 edge_index (values < 2^31): odd 32-bit words of the first lanes are all
// zero. int32: those words are random node ids (P(all zero) ~ 0).
__device__ __forceinline__ bool detect64(const int* __restrict__ ei) {
    int acc = 0;
#pragma unroll
    for (int i = 1; i < 16; i += 2) acc |= ei[i];
    return acc == 0;
}

// ---------------- fused GEMM + alpha  ⊕  edge histogram (heterogeneous blocks)
// blocks [0, gemmBlocks): 64-node GEMM tile (256 thr, 4x4 register block,
//   K-chunked 64x64 W buffer, float4 X loads in the inner loop).
// blocks [gemmBlocks, ...): histogram, 4 edges/thread via int4 loads.
template <int FIN, int H, bool DOHIST>
__global__ void gemm_alpha_kernel(const float* __restrict__ X,
                                  const float* __restrict__ W,
                                  const float* __restrict__ As,
                                  const float* __restrict__ Ad,
                                  const int* __restrict__ ei,
                                  int gemmBlocks) {
    if (DOHIST && blockIdx.x >= gemmBlocks) {
        int t = (blockIdx.x - gemmBlocks) * 256 + threadIdx.x;
        int e0 = t * 4;
        if (e0 < EE) {
            int d[4];
            if (detect64(ei)) {
                const int4* p = (const int4*)(ei + 2 * (EE + e0));
                int4 v0 = p[0], v1 = p[1];
                d[0] = v0.x; d[1] = v0.z; d[2] = v1.x; d[3] = v1.z;
            } else {
                int4 v = *(const int4*)(ei + EE + e0);
                d[0] = v.x; d[1] = v.y; d[2] = v.z; d[3] = v.w;
            }
#pragma unroll
            for (int q = 0; q < 4; q++) atomicAdd(&g_deg[d[q]], 1);
        }
        return;
    }

    extern __shared__ float smem[];
    float* sW = smem;               // 64*64
    float* sX = smem + 64 * 64;     // 64*(FIN+4)
    const int ROWS = FIN + 4;       // x4B is 16B-multiple -> float4 loads legal

    const int tid = threadIdx.x;
    const int node0 = blockIdx.x * 64;

    const int KV4 = FIN / 4;
    for (int i = tid; i < 64 * KV4; i += 256) {
        int r = i / KV4, c = i % KV4;
        int node = node0 + r;
        float4 v = (node < NN) ? ((const float4*)(X + (size_t)node * FIN))[c]
                               : make_float4(0.f, 0.f, 0.f, 0.f);
        *(float4*)&sX[r * ROWS + c * 4] = v;
    }

    const int tx = tid & 15;
    const int ty = tid >> 4;
    float acc[4][4];
#pragma unroll
    for (int i = 0; i < 4; i++)
#pragma unroll
        for (int j = 0; j < 4; j++) acc[i][j] = 0.f;

#pragma unroll
    for (int ch = 0; ch < FIN / 64; ch++) {
        __syncthreads();
        for (int i = tid; i < 64 * 16; i += 256) {
            float4 v = ((const float4*)(W + ch * 64 * 64))[i];
            *(float4*)&sW[i * 4] = v;
        }
        __syncthreads();

#pragma unroll 4
        for (int kk = 0; kk < 16; kk++) {
            float4 w0 = *(const float4*)&sW[(kk * 4 + 0) * 64 + tx * 4];
            float4 w1 = *(const float4*)&sW[(kk * 4 + 1) * 64 + tx * 4];
            float4 w2 = *(const float4*)&sW[(kk * 4 + 2) * 64 + tx * 4];
            float4 w3 = *(const float4*)&sW[(kk * 4 + 3) * 64 + tx * 4];
#pragma unroll
            for (int i = 0; i < 4; i++) {
                float4 xv = *(const float4*)&sX[(ty * 4 + i) * ROWS + ch * 64 + kk * 4];
                acc[i][0] += xv.x * w0.x + xv.y * w1.x + xv.z * w2.x + xv.w * w3.x;
                acc[i][1] += xv.x * w0.y + xv.y * w1.y + xv.z * w2.y + xv.w * w3.y;
                acc[i][2] += xv.x * w0.z + xv.y * w1.z + xv.z * w2.z + xv.w * w3.z;
                acc[i][3] += xv.x * w0.w + xv.y * w1.w + xv.z * w2.w + xv.w * w3.w;
            }
        }
    }
    __syncthreads();

#pragma unroll
    for (int i = 0; i < 4; i++) {
        int node = node0 + ty * 4 + i;
        if (node < NN) {
            *(float4*)&g_h[node * 64 + tx * 4] =
                make_float4(acc[i][0], acc[i][1], acc[i][2], acc[i][3]);
        }
        *(float4*)&sX[(ty * 4 + i) * ROWS + tx * 4] =
            make_float4(acc[i][0], acc[i][1], acc[i][2], acc[i][3]);
    }
    __syncthreads();

    if (H == 4) {
        int local = tid >> 2, head = tid & 3;
        int node = node0 + local;
        const float* hrow = &sX[local * ROWS + head * 16];
        float s = 0.f, d = 0.f;
#pragma unroll
        for (int f = 0; f < 16; f++) {
            float hv = hrow[f];
            s += hv * As[head * 16 + f];
            d += hv * Ad[head * 16 + f];
        }
        if (node < NN) {
            g_as[node * 4 + head] = s;
            g_ad[node * 4 + head] = d;
        }
    } else {
        int local = tid >> 2, q = tid & 3;
        int node = node0 + local;
        const float* hrow = &sX[local * ROWS + q * 16];
        float s = 0.f, d = 0.f;
#pragma unroll
        for (int f = 0; f < 16; f++) {
            float hv = hrow[f];
            s += hv * As[q * 16 + f];
            d += hv * Ad[q * 16 + f];
        }
        s += __shfl_xor_sync(0xFFFFFFFFu, s, 1);
        s += __shfl_xor_sync(0xFFFFFFFFu, s, 2);
        d += __shfl_xor_sync(0xFFFFFFFFu, d, 1);
        d += __shfl_xor_sync(0xFFFFFFFFu, d, 2);
        if (q == 0 && node < NN) {
            g_as[node] = s;
            g_ad[node] = d;
        }
    }
}

// ---------------- CSR build -----------------------------------------------------
// single-block exclusive scan of g_deg -> g_off, also seeds g_cursor
__global__ void scan_kernel() {
    __shared__ int part[1024];
    const int CH = (NN + 1023) / 1024;
    int t = threadIdx.x;
    int b0 = t * CH;
    int sum = 0;
    for (int i = 0; i < CH; i++) {
        int idx = b0 + i;
        if (idx < NN) sum += g_deg[idx];
    }
    part[t] = sum;
    __syncthreads();
    for (int off = 1; off < 1024; off <<= 1) {
        int v = (t >= off) ? part[t - off] : 0;
        __syncthreads();
        part[t] += v;
        __syncthreads();
    }
    int run = (t > 0) ? part[t - 1] : 0;
    for (int i = 0; i < CH; i++) {
        int idx = b0 + i;
        if (idx < NN) {
            g_off[idx] = run;
            g_cursor[idx] = run;
            run += g_deg[idx];
        }
    }
    if (t == 1023) g_off[NN] = EE;
}

// scatter, 1 edge/thread (max thread count; latency-bound);
// also re-zeroes g_deg for the next call (replay-invariant)
__global__ void scatter_kernel(const int* __restrict__ ei) {
    int e = blockIdx.x * blockDim.x + threadIdx.x;
    if (e >= EE) return;
    if (e < NN) g_deg[e] = 0;
    bool is64 = detect64(ei);
    int s, d;
    if (is64) { s = ei[2 * e]; d = ei[2 * (EE + e)]; }
    else      { s = ei[e];     d = ei[EE + e]; }
    int pos = atomicAdd(&g_cursor[d], 1);
    g_csrc[pos] = s;
}

// ---------------- CSR gather: two-phase warp algorithm -------------------------
// __launch_bounds__(256,8): cap regs at 32 -> 2048 thr/SM (occ was reg-capped
// at 63.8% with 40 regs; issue=60% says more warps -> more hidden latency).
// Phase 1: one lane per edge: coalesced csrc load, float4 alpha load, 4 exps,
//   weights -> warp smem, per-lane den4; also precompute s*64 for phase 2.
// Phase 2: half-warps sweep edges, h-row base offset shuffled directly.
// Unshifted softmax (weights are small): w = exp(lrelu(as[s]+ad[d])).
template <int H, bool ELU>
__global__ void __launch_bounds__(256, 8)
gather_kernel(const float* __restrict__ bias, float* __restrict__ out) {
    const unsigned FULL = 0xFFFFFFFFu;
    __shared__ float sw[8][(H == 4) ? 128 : 32];
    int d = (blockIdx.x * blockDim.x + threadIdx.x) >> 5;
    if (d >= NN) return;
    const int lane = threadIdx.x & 31;
    const int half = lane >> 4;
    const int j = lane & 15;
    const int head = (H == 4) ? (j >> 2) : 0;
    float* swp = sw[threadIdx.x >> 5];

    const int start = g_off[d];
    const int deg   = g_off[d + 1] - start;
    float4 acc = make_float4(0.f, 0.f, 0.f, 0.f);

    if (H == 4) {
        float4 ad4 = *(const float4*)&g_ad[d * 4];
        float4 a   = *(const float4*)&g_as[d * 4];
        float4 ws;
        ws.x = __expf(lrelu(a.x + ad4.x));
        ws.y = __expf(lrelu(a.y + ad4.y));
        ws.z = __expf(lrelu(a.z + ad4.z));
        ws.w = __expf(lrelu(a.w + ad4.w));
        float4 den4 = (lane == 0) ? ws : make_float4(0.f, 0.f, 0.f, 0.f);
        if (half == 0) {   // self-loop contribution
            float w = (head == 0) ? ws.x : (head == 1) ? ws.y
                    : (head == 2) ? ws.z : ws.w;
            float4 hv = *(const float4*)&g_h[d * 64 + j * 4];
            acc.x = w * hv.x; acc.y = w * hv.y;
            acc.z = w * hv.z; acc.w = w * hv.w;
        }

        for (int base = 0; base < deg; base += 32) {
            int cnt = min(32, deg - base);
            int s64 = 0;
            if (lane < cnt) {
                int s = g_csrc[start + base + lane];
                float4 a2 = *(const float4*)&g_as[s * 4];
                s64 = s * 64;
                float4 w;
                w.x = __expf(lrelu(a2.x + ad4.x));
                w.y = __expf(lrelu(a2.y + ad4.y));
                w.z = __expf(lrelu(a2.z + ad4.z));
                w.w = __expf(lrelu(a2.w + ad4.w));
                den4.x += w.x; den4.y += w.y; den4.z += w.z; den4.w += w.w;
                *(float4*)&swp[lane * 4] = w;
            }
            __syncwarp();
            int nit = (cnt + 1) >> 1;
            for (int it = 0; it < nit; it++) {
                int ee = it * 2 + half;
                int se64 = __shfl_sync(FULL, s64, ee & 31);
                if (ee < cnt) {
                    float w = swp[ee * 4 + head];
                    float4 hv = *(const float4*)&g_h[se64 + j * 4];
                    acc.x += w * hv.x; acc.y += w * hv.y;
                    acc.z += w * hv.z; acc.w += w * hv.w;
                }
            }
            __syncwarp();
        }

#pragma unroll
        for (int off = 16; off >= 1; off >>= 1) {
            den4.x += __shfl_xor_sync(FULL, den4.x, off);
            den4.y += __shfl_xor_sync(FULL, den4.y, off);
            den4.z += __shfl_xor_sync(FULL, den4.z, off);
            den4.w += __shfl_xor_sync(FULL, den4.w, off);
        }
        acc.x += __shfl_xor_sync(FULL, acc.x, 16);
        acc.y += __shfl_xor_sync(FULL, acc.y, 16);
        acc.z += __shfl_xor_sync(FULL, acc.z, 16);
        acc.w += __shfl_xor_sync(FULL, acc.w, 16);

        if (half == 0) {
            float den = (head == 0) ? den4.x : (head == 1) ? den4.y
                      : (head == 2) ? den4.z : den4.w;
            float inv = 1.f / (den + 1e-16f);
            float4 bv = *(const float4*)&bias[j * 4];
            float4 v;
            v.x = acc.x * inv + bv.x; v.y = acc.y * inv + bv.y;
            v.z = acc.z * inv + bv.z; v.w = acc.w * inv + bv.w;
            if (ELU) {
                v.x = v.x > 0.f ? v.x : expm1f(v.x);
                v.y = v.y > 0.f ? v.y : expm1f(v.y);
                v.z = v.z > 0.f ? v.z : expm1f(v.z);
                v.w = v.w > 0.f ? v.w : expm1f(v.w);
            }
            *(float4*)&out[d * 64 + j * 4] = v;
        }
    } else {
        float adv = g_ad[d];
        float ws  = __expf(lrelu(g_as[d] + adv));
        float den = (lane == 0) ? ws : 0.f;
        if (half == 0) {
            float4 hv = *(const float4*)&g_h[d * 64 + j * 4];
            acc.x = ws * hv.x; acc.y = ws * hv.y;
            acc.z = ws * hv.z; acc.w = ws * hv.w;
        }

        for (int base = 0; base < deg; base += 32) {
            int cnt = min(32, deg - base);
            int s64 = 0;
            if (lane < cnt) {
                int s = g_csrc[start + base + lane];
                float w = __expf(lrelu(g_as[s] + adv));
                s64 = s * 64;
                den += w;
                swp[lane] = w;
            }
            __syncwarp();
            int nit = (cnt + 1) >> 1;
            for (int it = 0; it < nit; it++) {
                int ee = it * 2 + half;
                int se64 = __shfl_sync(FULL, s64, ee & 31);
                if (ee < cnt) {
                    float w = swp[ee];
                    float4 hv = *(const float4*)&g_h[se64 + j * 4];
                    acc.x += w * hv.x; acc.y += w * hv.y;
                    acc.z += w * hv.z; acc.w += w * hv.w;
                }
            }
            __syncwarp();
        }

#pragma unroll
        for (int off = 16; off >= 1; off >>= 1)
            den += __shfl_xor_sync(FULL, den, off);
        acc.x += __shfl_xor_sync(FULL, acc.x, 16);
        acc.y += __shfl_xor_sync(FULL, acc.y, 16);
        acc.z += __shfl_xor_sync(FULL, acc.z, 16);
        acc.w += __shfl_xor_sync(FULL, acc.w, 16);

        if (half == 0) {
            float inv = 1.f / (den + 1e-16f);
            float4 bv = *(const float4*)&bias[j * 4];
            float4 v;
            v.x = acc.x * inv + bv.x; v.y = acc.y * inv + bv.y;
            v.z = acc.z * inv + bv.z; v.w = acc.w * inv + bv.w;
            *(float4*)&out[d * 64 + j * 4] = v;
        }
    }
}

// ---------------- launch -------------------------------------------------------
extern "C" void kernel_launch(void* const* d_in, const int* in_sizes, int n_in,
                              void* d_out, int out_size) {
    const float* x   = (const float*)d_in[0];
    const int*   ei  = (const int*)d_in[1];
    const float* W0  = (const float*)d_in[2];
    const float* as0 = (const float*)d_in[3];
    const float* ad0 = (const float*)d_in[4];
    const float* b0  = (const float*)d_in[5];
    const float* W1  = (const float*)d_in[6];
    const float* as1 = (const float*)d_in[7];
    const float* ad1 = (const float*)d_in[8];
    const float* b1  = (const float*)d_in[9];
    const float* W2  = (const float*)d_in[10];
    const float* as2 = (const float*)d_in[11];
    const float* ad2 = (const float*)d_in[12];
    const float* b2  = (const float*)d_in[13];
    float* out = (float*)d_out;

    float *featA, *featB;
    cudaGetSymbolAddress((void**)&featA, g_featA);
    cudaGetSymbolAddress((void**)&featB, g_featB);

    const int smem128 = (64 * 64 + 64 * 132) * 4;   // 50176 B
    const int smem64  = (64 * 64 + 64 * 68) * 4;    // 33792 B
    cudaFuncSetAttribute(gemm_alpha_kernel<128, 4, true>,
                         cudaFuncAttributeMaxDynamicSharedMemorySize, smem128);
    cudaFuncSetAttribute(gemm_alpha_kernel<64, 4, false>,
                         cudaFuncAttributeMaxDynamicSharedMemorySize, smem64);
    cudaFuncSetAttribute(gemm_alpha_kernel<64, 1, false>,
                         cudaFuncAttributeMaxDynamicSharedMemorySize, smem64);

    const int gemm_grid = (NN + 63) / 64;            // 782
    const int hist_grid = (EE / 4 + 255) / 256;      // 782 (4 edges/thread)
    const int edge_grid = (EE + 255) / 256;          // 3125
    const int gath_grid = (NN * 32 + 255) / 256;

    // K1: layer-0 GEMM ⊕ edge histogram (independent work, heterogeneous blocks)
    gemm_alpha_kernel<128, 4, true>
        <<<gemm_grid + hist_grid, 256, smem128>>>(x, W0, as0, ad0, ei, gemm_grid);
    scan_kernel<<<1, 1024>>>();                      // K2
    scatter_kernel<<<edge_grid, 256>>>(ei);          // K3 (also re-zeroes g_deg)
    gather_kernel<4, true><<<gath_grid, 256>>>(b0, featA);   // K4 -> profiled

    // layer 1 : 64 -> 4x16, ELU
    gemm_alpha_kernel<64, 4, false>
        <<<gemm_grid, 256, smem64>>>(featA, W1, as1, ad1, ei, gemm_grid);
    gather_kernel<4, true><<<gath_grid, 256>>>(b1, featB);

    // layer 2 : 64 -> 1x64, no ELU
    gemm_alpha_kernel<64, 1, false>
        <<<gemm_grid, 256, smem64>>>(featB, W2, as2, ad2, ei, gemm_grid);
    gather_kernel<1, false><<<gath_grid, 256>>>(b2, out);
}

// round 14
// speedup vs baseline: 1.3424x; 1.3424x over previous
#include <cuda_runtime.h>

#define NN 50000
#define EE 800000
#define NEG 0.2f

// ---------------- scratch (device globals) ----------------------------------
__device__ __align__(16) int   g_csrc[EE];      // CSR: src ids grouped by dst
__device__ __align__(16) int   g_deg[NN];        // zero-init; re-zeroed by scatter
__device__ int   g_off[NN];                      // segment start per node
__device__ int   g_end[NN];                      // segment end per node
__device__ int   g_cursor[NN];
__device__ __align__(16) float g_h[NN * 64];
__device__ __align__(16) float g_featA[NN * 64];
__device__ __align__(16) float g_featB[NN * 64];
__device__ __align__(16) float g_as[NN * 4];
__device__ __align__(16) float g_ad[NN * 4];

// lrelu(x) == max(x, 0.2x)  (2 instr: FMUL + FMNMX)
__device__ __forceinline__ float lrelu(float x) { return fmaxf(x, NEG * x); }

// int64 edge_index (values < 2^31): odd 32-bit words of the first lanes are all
// zero. int32: those words are random node ids (P(all zero) ~ 0).
__device__ __forceinline__ bool detect64(const int* __restrict__ ei) {
    int acc = 0;
#pragma unroll
    for (int i = 1; i < 16; i += 2) acc |= ei[i];
    return acc == 0;
}

// ---------------- fused GEMM + alpha  ⊕  edge histogram (heterogeneous blocks)
// blocks [0, gemmBlocks): 64-node GEMM tile (256 thr, 4x4 register block,
//   K-chunked 64x64 W buffer in smem).
// blocks [gemmBlocks, ...): histogram, 4 edges/thread via int4 loads.
template <int FIN, int H, bool DOHIST>
__global__ void gemm_alpha_kernel(const float* __restrict__ X,
                                  const float* __restrict__ W,
                                  const float* __restrict__ As,
                                  const float* __restrict__ Ad,
                                  const int* __restrict__ ei,
                                  int gemmBlocks) {
    if (DOHIST && blockIdx.x >= gemmBlocks) {
        int t = (blockIdx.x - gemmBlocks) * 256 + threadIdx.x;
        int e0 = t * 4;
        if (e0 < EE) {
            int d[4];
            if (detect64(ei)) {
                const int4* p = (const int4*)(ei + 2 * (EE + e0));
                int4 v0 = p[0], v1 = p[1];
                d[0] = v0.x; d[1] = v0.z; d[2] = v1.x; d[3] = v1.z;
            } else {
                int4 v = *(const int4*)(ei + EE + e0);
                d[0] = v.x; d[1] = v.y; d[2] = v.z; d[3] = v.w;
            }
#pragma unroll
            for (int q = 0; q < 4; q++) atomicAdd(&g_deg[d[q]], 1);
        }
        return;
    }

    extern __shared__ float smem[];
    float* sW = smem;               // 64*64
    float* sX = smem + 64 * 64;     // 64*(FIN+4)
    const int ROWS = FIN + 4;

    const int tid = threadIdx.x;
    const int node0 = blockIdx.x * 64;

    const int KV4 = FIN / 4;
    for (int i = tid; i < 64 * KV4; i += 256) {
        int r = i / KV4, c = i % KV4;
        int node = node0 + r;
        float4 v = (node < NN) ? ((const float4*)(X + (size_t)node * FIN))[c]
                               : make_float4(0.f, 0.f, 0.f, 0.f);
        *(float4*)&sX[r * ROWS + c * 4] = v;
    }

    const int tx = tid & 15;
    const int ty = tid >> 4;
    float acc[4][4];
#pragma unroll
    for (int i = 0; i < 4; i++)
#pragma unroll
        for (int j = 0; j < 4; j++) acc[i][j] = 0.f;

#pragma unroll
    for (int ch = 0; ch < FIN / 64; ch++) {
        __syncthreads();
        for (int i = tid; i < 64 * 16; i += 256) {
            float4 v = ((const float4*)(W + ch * 64 * 64))[i];
            *(float4*)&sW[i * 4] = v;
        }
        __syncthreads();

#pragma unroll 8
        for (int k = 0; k < 64; k++) {
            float4 w4 = *(const float4*)&sW[k * 64 + tx * 4];
#pragma unroll
            for (int i = 0; i < 4; i++) {
                float xv = sX[(ty * 4 + i) * ROWS + ch * 64 + k];
                acc[i][0] += xv * w4.x;
                acc[i][1] += xv * w4.y;
                acc[i][2] += xv * w4.z;
                acc[i][3] += xv * w4.w;
            }
        }
    }
    __syncthreads();

#pragma unroll
    for (int i = 0; i < 4; i++) {
        int node = node0 + ty * 4 + i;
        if (node < NN) {
            *(float4*)&g_h[node * 64 + tx * 4] =
                make_float4(acc[i][0], acc[i][1], acc[i][2], acc[i][3]);
        }
        *(float4*)&sX[(ty * 4 + i) * ROWS + tx * 4] =
            make_float4(acc[i][0], acc[i][1], acc[i][2], acc[i][3]);
    }
    __syncthreads();

    if (H == 4) {
        int local = tid >> 2, head = tid & 3;
        int node = node0 + local;
        const float* hrow = &sX[local * ROWS + head * 16];
        float s = 0.f, d = 0.f;
#pragma unroll
        for (int f = 0; f < 16; f++) {
            float hv = hrow[f];
            s += hv * As[head * 16 + f];
            d += hv * Ad[head * 16 + f];
        }
        if (node < NN) {
            g_as[node * 4 + head] = s;
            g_ad[node * 4 + head] = d;
        }
    } else {
        int local = tid >> 2, q = tid & 3;
        int node = node0 + local;
        const float* hrow = &sX[local * ROWS + q * 16];
        float s = 0.f, d = 0.f;
#pragma unroll
        for (int f = 0; f < 16; f++) {
            float hv = hrow[f];
            s += hv * As[q * 16 + f];
            d += hv * Ad[q * 16 + f];
        }
        s += __shfl_xor_sync(0xFFFFFFFFu, s, 1);
        s += __shfl_xor_sync(0xFFFFFFFFu, s, 2);
        d += __shfl_xor_sync(0xFFFFFFFFu, d, 1);
        d += __shfl_xor_sync(0xFFFFFFFFu, d, 2);
        if (q == 0 && node < NN) {
            g_as[node] = s;
            g_ad[node] = d;
        }
    }
}

// ---------------- CSR build -----------------------------------------------------
// Single-block scan with COALESCED interleaved ownership: thread t owns nodes
// t, 1024+t, 2048+t, ... Segment placement is permuted vs node id (allowed:
// gather reads [g_off[d], g_end[d]) explicitly). Both g_deg passes and all
// g_off/g_end/g_cursor writes are fully coalesced.
__global__ void scan_kernel() {
    __shared__ int part[1024];
    const int ITER = (NN + 1023) / 1024;
    int t = threadIdx.x;
    int sum = 0;
    for (int i = 0; i < ITER; i++) {
        int idx = i * 1024 + t;
        if (idx < NN) sum += g_deg[idx];
    }
    part[t] = sum;
    __syncthreads();
    for (int off = 1; off < 1024; off <<= 1) {
        int v = (t >= off) ? part[t - off] : 0;
        __syncthreads();
        part[t] += v;
        __syncthreads();
    }
    int run = (t > 0) ? part[t - 1] : 0;
    for (int i = 0; i < ITER; i++) {
        int idx = i * 1024 + t;
        if (idx < NN) {
            int dg = g_deg[idx];
            g_off[idx] = run;
            g_end[idx] = run + dg;
            g_cursor[idx] = run;
            run += dg;
        }
    }
}

// scatter, 1 edge/thread (max thread count; latency-bound);
// also re-zeroes g_deg for the next call (replay-invariant)
__global__ void scatter_kernel(const int* __restrict__ ei) {
    int e = blockIdx.x * blockDim.x + threadIdx.x;
    if (e >= EE) return;
    if (e < NN) g_deg[e] = 0;
    bool is64 = detect64(ei);
    int s, d;
    if (is64) { s = ei[2 * e]; d = ei[2 * (EE + e)]; }
    else      { s = ei[e];     d = ei[EE + e]; }
    int pos = atomicAdd(&g_cursor[d], 1);
    g_csrc[pos] = s;
}

// ---------------- CSR gather: two-phase warp algorithm (R12 form) -------------
// Warp per destination. Phase 1: one lane per edge: coalesced csrc load,
// float4 alpha load, 4 exps -> weights in warp smem, per-lane den4.
// Phase 2: half-warps sweep the chunk accumulating w*h[src].
// Unshifted softmax (weights are small): w = exp(max(x, 0.2x)).
// ELU epilogue via __expf(v)-1 (expm1f is a ~20-instr polynomial; error at
// v->0- is ~1e-7 absolute, invisible at the 1e-3 threshold).
template <int H, bool ELU>
__global__ void gather_kernel(const float* __restrict__ bias,
                              float* __restrict__ out) {
    const unsigned FULL = 0xFFFFFFFFu;
    __shared__ float sw[8][(H == 4) ? 128 : 32];
    int d = (blockIdx.x * blockDim.x + threadIdx.x) >> 5;
    if (d >= NN) return;
    const int lane = threadIdx.x & 31;
    const int half = lane >> 4;
    const int j = lane & 15;
    const int head = (H == 4) ? (j >> 2) : 0;
    float* swp = sw[threadIdx.x >> 5];

    const int start = g_off[d];
    const int deg   = g_end[d] - start;
    float4 acc = make_float4(0.f, 0.f, 0.f, 0.f);

    if (H == 4) {
        float4 ad4 = *(const float4*)&g_ad[d * 4];
        float4 a   = *(const float4*)&g_as[d * 4];
        float4 ws;
        ws.x = __expf(lrelu(a.x + ad4.x));
        ws.y = __expf(lrelu(a.y + ad4.y));
        ws.z = __expf(lrelu(a.z + ad4.z));
        ws.w = __expf(lrelu(a.w + ad4.w));
        float4 den4 = (lane == 0) ? ws : make_float4(0.f, 0.f, 0.f, 0.f);
        if (half == 0) {   // self-loop contribution
            float w = (head == 0) ? ws.x : (head == 1) ? ws.y
                    : (head == 2) ? ws.z : ws.w;
            float4 hv = *(const float4*)&g_h[d * 64 + j * 4];
            acc.x = w * hv.x; acc.y = w * hv.y;
            acc.z = w * hv.z; acc.w = w * hv.w;
        }

        for (int base = 0; base < deg; base += 32) {
            int cnt = min(32, deg - base);
            int s = 0;
            if (lane < cnt) {
                s = g_csrc[start + base + lane];
                float4 a2 = *(const float4*)&g_as[s * 4];
                float4 w;
                w.x = __expf(lrelu(a2.x + ad4.x));
                w.y = __expf(lrelu(a2.y + ad4.y));
                w.z = __expf(lrelu(a2.z + ad4.z));
                w.w = __expf(lrelu(a2.w + ad4.w));
                den4.x += w.x; den4.y += w.y; den4.z += w.z; den4.w += w.w;
                *(float4*)&swp[lane * 4] = w;
            }
            __syncwarp();
            int nit = (cnt + 1) >> 1;
            for (int it = 0; it < nit; it++) {
                int ee = it * 2 + half;
                int se = __shfl_sync(FULL, s, ee & 31);
                if (ee < cnt) {
                    float w = swp[ee * 4 + head];
                    float4 hv = *(const float4*)&g_h[se * 64 + j * 4];
                    acc.x += w * hv.x; acc.y += w * hv.y;
                    acc.z += w * hv.z; acc.w += w * hv.w;
                }
            }
            __syncwarp();
        }

#pragma unroll
        for (int off = 16; off >= 1; off >>= 1) {
            den4.x += __shfl_xor_sync(FULL, den4.x, off);
            den4.y += __shfl_xor_sync(FULL, den4.y, off);
            den4.z += __shfl_xor_sync(FULL, den4.z, off);
            den4.w += __shfl_xor_sync(FULL, den4.w, off);
        }
        acc.x += __shfl_xor_sync(FULL, acc.x, 16);
        acc.y += __shfl_xor_sync(FULL, acc.y, 16);
        acc.z += __shfl_xor_sync(FULL, acc.z, 16);
        acc.w += __shfl_xor_sync(FULL, acc.w, 16);

        if (half == 0) {
            float den = (head == 0) ? den4.x : (head == 1) ? den4.y
                      : (head == 2) ? den4.z : den4.w;
            float inv = 1.f / (den + 1e-16f);
            float4 bv = *(const float4*)&bias[j * 4];
            float4 v;
            v.x = acc.x * inv + bv.x; v.y = acc.y * inv + bv.y;
            v.z = acc.z * inv + bv.z; v.w = acc.w * inv + bv.w;
            if (ELU) {
                v.x = v.x > 0.f ? v.x : (__expf(v.x) - 1.f);
                v.y = v.y > 0.f ? v.y : (__expf(v.y) - 1.f);
                v.z = v.z > 0.f ? v.z : (__expf(v.z) - 1.f);
                v.w = v.w > 0.f ? v.w : (__expf(v.w) - 1.f);
            }
            *(float4*)&out[d * 64 + j * 4] = v;
        }
    } else {
        float adv = g_ad[d];
        float ws  = __expf(lrelu(g_as[d] + adv));
        float den = (lane == 0) ? ws : 0.f;
        if (half == 0) {
            float4 hv = *(const float4*)&g_h[d * 64 + j * 4];
            acc.x = ws * hv.x; acc.y = ws * hv.y;
            acc.z = ws * hv.z; acc.w = ws * hv.w;
        }

        for (int base = 0; base < deg; base += 32) {
            int cnt = min(32, deg - base);
            int s = 0;
            if (lane < cnt) {
                s = g_csrc[start + base + lane];
                float w = __expf(lrelu(g_as[s] + adv));
                den += w;
                swp[lane] = w;
            }
            __syncwarp();
            int nit = (cnt + 1) >> 1;
            for (int it = 0; it < nit; it++) {
                int ee = it * 2 + half;
                int se = __shfl_sync(FULL, s, ee & 31);
                if (ee < cnt) {
                    float w = swp[ee];
                    float4 hv = *(const float4*)&g_h[se * 64 + j * 4];
                    acc.x += w * hv.x; acc.y += w * hv.y;
                    acc.z += w * hv.z; acc.w += w * hv.w;
                }
            }
            __syncwarp();
        }

#pragma unroll
        for (int off = 16; off >= 1; off >>= 1)
            den += __shfl_xor_sync(FULL, den, off);
        acc.x += __shfl_xor_sync(FULL, acc.x, 16);
        acc.y += __shfl_xor_sync(FULL, acc.y, 16);
        acc.z += __shfl_xor_sync(FULL, acc.z, 16);
        acc.w += __shfl_xor_sync(FULL, acc.w, 16);

        if (half == 0) {
            float inv = 1.f / (den + 1e-16f);
            float4 bv = *(const float4*)&bias[j * 4];
            float4 v;
            v.x = acc.x * inv + bv.x; v.y = acc.y * inv + bv.y;
            v.z = acc.z * inv + bv.z; v.w = acc.w * inv + bv.w;
            *(float4*)&out[d * 64 + j * 4] = v;
        }
    }
}

// ---------------- launch -------------------------------------------------------
extern "C" void kernel_launch(void* const* d_in, const int* in_sizes, int n_in,
                              void* d_out, int out_size) {
    const float* x   = (const float*)d_in[0];
    const int*   ei  = (const int*)d_in[1];
    const float* W0  = (const float*)d_in[2];
    const float* as0 = (const float*)d_in[3];
    const float* ad0 = (const float*)d_in[4];
    const float* b0  = (const float*)d_in[5];
    const float* W1  = (const float*)d_in[6];
    const float* as1 = (const float*)d_in[7];
    const float* ad1 = (const float*)d_in[8];
    const float* b1  = (const float*)d_in[9];
    const float* W2  = (const float*)d_in[10];
    const float* as2 = (const float*)d_in[11];
    const float* ad2 = (const float*)d_in[12];
    const float* b2  = (const float*)d_in[13];
    float* out = (float*)d_out;

    float *featA, *featB;
    cudaGetSymbolAddress((void**)&featA, g_featA);
    cudaGetSymbolAddress((void**)&featB, g_featB);

    const int smem128 = (64 * 64 + 64 * 132) * 4;   // 50176 B
    const int smem64  = (64 * 64 + 64 * 68) * 4;    // 33792 B
    cudaFuncSetAttribute(gemm_alpha_kernel<128, 4, true>,
                         cudaFuncAttributeMaxDynamicSharedMemorySize, smem128);
    cudaFuncSetAttribute(gemm_alpha_kernel<64, 4, false>,
                         cudaFuncAttributeMaxDynamicSharedMemorySize, smem64);
    cudaFuncSetAttribute(gemm_alpha_kernel<64, 1, false>,
                         cudaFuncAttributeMaxDynamicSharedMemorySize, smem64);

    const int gemm_grid = (NN + 63) / 64;            // 782
    const int hist_grid = (EE / 4 + 255) / 256;      // 782 (4 edges/thread)
    const int edge_grid = (EE + 255) / 256;          // 3125
    const int gath_grid = (NN * 32 + 255) / 256;

    // K1: layer-0 GEMM ⊕ edge histogram (independent work, heterogeneous blocks)
    gemm_alpha_kernel<128, 4, true>
        <<<gemm_grid + hist_grid, 256, smem128>>>(x, W0, as0, ad0, ei, gemm_grid);
    scan_kernel<<<1, 1024>>>();                      // K2
    scatter_kernel<<<edge_grid, 256>>>(ei);          // K3 (also re-zeroes g_deg)
    gather_kernel<4, true><<<gath_grid, 256>>>(b0, featA);   // K4 -> profiled

    // layer 1 : 64 -> 4x16, ELU
    gemm_alpha_kernel<64, 4, false>
        <<<gemm_grid, 256, smem64>>>(featA, W1, as1, ad1, ei, gemm_grid);
    gather_kernel<4, true><<<gath_grid, 256>>>(b1, featB);

    // layer 2 : 64 -> 1x64, no ELU
    gemm_alpha_kernel<64, 1, false>
        <<<gemm_grid, 256, smem64>>>(featB, W2, as2, ad2, ei, gemm_grid);
    gather_kernel<1, false><<<gath_grid, 256>>>(b2, out);
}

// round 15
// speedup vs baseline: 1.3616x; 1.0143x over previous
#include <cuda_runtime.h>

#define NN 50000
#define EE 800000
#define NEG 0.2f

// ---------------- scratch (device globals) ----------------------------------
__device__ __align__(16) int   g_csrc[EE];      // CSR: src ids grouped by dst
__device__ __align__(16) int   g_deg[NN];        // zero-init; re-zeroed by scatter
__device__ int   g_off[NN];                      // segment start per node
__device__ int   g_end[NN];                      // segment end per node
__device__ int   g_cursor[NN];
__device__ __align__(16) float g_h[NN * 64];
__device__ __align__(16) float g_featA[NN * 64];
__device__ __align__(16) float g_featB[NN * 64];
__device__ __align__(16) float g_as[NN * 4];
__device__ __align__(16) float g_ad[NN * 4];

// lrelu(x) == max(x, 0.2x)
__device__ __forceinline__ float lrelu(float x) { return fmaxf(x, NEG * x); }

// int64 edge_index (values < 2^31): odd 32-bit words of the first lanes are all
// zero. int32: those words are random node ids (P(all zero) ~ 0).
__device__ __forceinline__ bool detect64(const int* __restrict__ ei) {
    int acc = 0;
#pragma unroll
    for (int i = 1; i < 16; i += 2) acc |= ei[i];
    return acc == 0;
}

// ---------------- fused GEMM + alpha  ⊕  edge histogram (heterogeneous blocks)
template <int FIN, int H, bool DOHIST>
__global__ void gemm_alpha_kernel(const float* __restrict__ X,
                                  const float* __restrict__ W,
                                  const float* __restrict__ As,
                                  const float* __restrict__ Ad,
                                  const int* __restrict__ ei,
                                  int gemmBlocks) {
    if (DOHIST && blockIdx.x >= gemmBlocks) {
        int t = (blockIdx.x - gemmBlocks) * 256 + threadIdx.x;
        int e0 = t * 4;
        if (e0 < EE) {
            int d[4];
            if (detect64(ei)) {
                const int4* p = (const int4*)(ei + 2 * (EE + e0));
                int4 v0 = p[0], v1 = p[1];
                d[0] = v0.x; d[1] = v0.z; d[2] = v1.x; d[3] = v1.z;
            } else {
                int4 v = *(const int4*)(ei + EE + e0);
                d[0] = v.x; d[1] = v.y; d[2] = v.z; d[3] = v.w;
            }
#pragma unroll
            for (int q = 0; q < 4; q++) atomicAdd(&g_deg[d[q]], 1);
        }
        return;
    }

    extern __shared__ float smem[];
    float* sW = smem;               // 64*64
    float* sX = smem + 64 * 64;     // 64*(FIN+4)
    const int ROWS = FIN + 4;

    const int tid = threadIdx.x;
    const int node0 = blockIdx.x * 64;

    const int KV4 = FIN / 4;
    for (int i = tid; i < 64 * KV4; i += 256) {
        int r = i / KV4, c = i % KV4;
        int node = node0 + r;
        float4 v = (node < NN) ? ((const float4*)(X + (size_t)node * FIN))[c]
                               : make_float4(0.f, 0.f, 0.f, 0.f);
        *(float4*)&sX[r * ROWS + c * 4] = v;
    }

    const int tx = tid & 15;
    const int ty = tid >> 4;
    float acc[4][4];
#pragma unroll
    for (int i = 0; i < 4; i++)
#pragma unroll
        for (int j = 0; j < 4; j++) acc[i][j] = 0.f;

#pragma unroll
    for (int ch = 0; ch < FIN / 64; ch++) {
        __syncthreads();
        for (int i = tid; i < 64 * 16; i += 256) {
            float4 v = ((const float4*)(W + ch * 64 * 64))[i];
            *(float4*)&sW[i * 4] = v;
        }
        __syncthreads();

#pragma unroll 8
        for (int k = 0; k < 64; k++) {
            float4 w4 = *(const float4*)&sW[k * 64 + tx * 4];
#pragma unroll
            for (int i = 0; i < 4; i++) {
                float xv = sX[(ty * 4 + i) * ROWS + ch * 64 + k];
                acc[i][0] += xv * w4.x;
                acc[i][1] += xv * w4.y;
                acc[i][2] += xv * w4.z;
                acc[i][3] += xv * w4.w;
            }
        }
    }
    __syncthreads();

#pragma unroll
    for (int i = 0; i < 4; i++) {
        int node = node0 + ty * 4 + i;
        if (node < NN) {
            *(float4*)&g_h[node * 64 + tx * 4] =
                make_float4(acc[i][0], acc[i][1], acc[i][2], acc[i][3]);
        }
        *(float4*)&sX[(ty * 4 + i) * ROWS + tx * 4] =
            make_float4(acc[i][0], acc[i][1], acc[i][2], acc[i][3]);
    }
    __syncthreads();

    if (H == 4) {
        int local = tid >> 2, head = tid & 3;
        int node = node0 + local;
        const float* hrow = &sX[local * ROWS + head * 16];
        float s = 0.f, d = 0.f;
#pragma unroll
        for (int f = 0; f < 16; f++) {
            float hv = hrow[f];
            s += hv * As[head * 16 + f];
            d += hv * Ad[head * 16 + f];
        }
        if (node < NN) {
            g_as[node * 4 + head] = s;
            g_ad[node * 4 + head] = d;
        }
    } else {
        int local = tid >> 2, q = tid & 3;
        int node = node0 + local;
        const float* hrow = &sX[local * ROWS + q * 16];
        float s = 0.f, d = 0.f;
#pragma unroll
        for (int f = 0; f < 16; f++) {
            float hv = hrow[f];
            s += hv * As[q * 16 + f];
            d += hv * Ad[q * 16 + f];
        }
        s += __shfl_xor_sync(0xFFFFFFFFu, s, 1);
        s += __shfl_xor_sync(0xFFFFFFFFu, s, 2);
        d += __shfl_xor_sync(0xFFFFFFFFu, d, 1);
        d += __shfl_xor_sync(0xFFFFFFFFu, d, 2);
        if (q == 0 && node < NN) {
            g_as[node] = s;
            g_ad[node] = d;
        }
    }
}

// ---------------- CSR build (coalesced interleaved scan) ----------------------
__global__ void scan_kernel() {
    __shared__ int part[1024];
    const int ITER = (NN + 1023) / 1024;
    int t = threadIdx.x;
    int sum = 0;
    for (int i = 0; i < ITER; i++) {
        int idx = i * 1024 + t;
        if (idx < NN) sum += g_deg[idx];
    }
    part[t] = sum;
    __syncthreads();
    for (int off = 1; off < 1024; off <<= 1) {
        int v = (t >= off) ? part[t - off] : 0;
        __syncthreads();
        part[t] += v;
        __syncthreads();
    }
    int run = (t > 0) ? part[t - 1] : 0;
    for (int i = 0; i < ITER; i++) {
        int idx = i * 1024 + t;
        if (idx < NN) {
            int dg = g_deg[idx];
            g_off[idx] = run;
            g_end[idx] = run + dg;
            g_cursor[idx] = run;
            run += dg;
        }
    }
}

// scatter, 1 edge/thread; also re-zeroes g_deg (replay-invariant)
__global__ void scatter_kernel(const int* __restrict__ ei) {
    int e = blockIdx.x * blockDim.x + threadIdx.x;
    if (e >= EE) return;
    if (e < NN) g_deg[e] = 0;
    bool is64 = detect64(ei);
    int s, d;
    if (is64) { s = ei[2 * e]; d = ei[2 * (EE + e)]; }
    else      { s = ei[e];     d = ei[EE + e]; }
    int pos = atomicAdd(&g_cursor[d], 1);
    g_csrc[pos] = s;
}

// ---------------- CSR gather: one destination per HALF-warp -------------------
// Warp handles 2 nodes; each 16-lane half owns node d = warp*2 + half fully:
// prologue/epilogue per node halves, no cross-half acc reduction, no idle
// lanes in the epilogue. Loop runs to max(deg_a, deg_b) with predication.
// Phase 1: lane j (0..15) loads csrc[start+base+j], computes w (4 exps for
// H=4), stores to half-private smem, accumulates den per lane.
// Phase 2: per edge it: s shuffled from lane half*16+it, w from smem, 1 LDG.128
// + 4 FFMA per lane (j = 4 cols/lane covers all 64 cols per half).
// Unshifted softmax (weights are small); ELU via __expf(v)-1.
template <int H, bool ELU>
__global__ void gather_kernel(const float* __restrict__ bias,
                              float* __restrict__ out) {
    const unsigned FULL = 0xFFFFFFFFu;
    __shared__ float sw[8][(H == 4) ? 128 : 32];
    int wrp = (blockIdx.x * blockDim.x + threadIdx.x) >> 5;
    const int lane = threadIdx.x & 31;
    const int half = lane >> 4;
    const int j = lane & 15;
    const int d = wrp * 2 + half;
    if (d >= NN) return;   // NN even, grid exact -> warp-uniform in practice
    const int head = (H == 4) ? (j >> 2) : 0;
    float* swp = sw[threadIdx.x >> 5] + half * ((H == 4) ? 64 : 16);

    const int start = g_off[d];
    const int deg   = g_end[d] - start;
    const int mdeg  = max(deg, __shfl_xor_sync(FULL, deg, 16));

    float4 acc;
    if (H == 4) {
        float4 ad4 = *(const float4*)&g_ad[d * 4];   // broadcast within half
        float4 a   = *(const float4*)&g_as[d * 4];
        float4 ws;
        ws.x = __expf(lrelu(a.x + ad4.x));
        ws.y = __expf(lrelu(a.y + ad4.y));
        ws.z = __expf(lrelu(a.z + ad4.z));
        ws.w = __expf(lrelu(a.w + ad4.w));
        float4 den4 = (j == 0) ? ws : make_float4(0.f, 0.f, 0.f, 0.f);

        // self-loop
        float wsl = (head == 0) ? ws.x : (head == 1) ? ws.y
                  : (head == 2) ? ws.z : ws.w;
        float4 hv = *(const float4*)&g_h[d * 64 + j * 4];
        acc.x = wsl * hv.x; acc.y = wsl * hv.y;
        acc.z = wsl * hv.z; acc.w = wsl * hv.w;

        for (int base = 0; base < mdeg; base += 16) {
            int cnt  = deg - base;            // may be <=0 for this half
            int s = 0;
            if (j < cnt) {
                s = g_csrc[start + base + j];
                float4 a2 = *(const float4*)&g_as[s * 4];
                float4 w;
                w.x = __expf(lrelu(a2.x + ad4.x));
                w.y = __expf(lrelu(a2.y + ad4.y));
                w.z = __expf(lrelu(a2.z + ad4.z));
                w.w = __expf(lrelu(a2.w + ad4.w));
                den4.x += w.x; den4.y += w.y; den4.z += w.z; den4.w += w.w;
                *(float4*)&swp[j * 4] = w;
            }
            __syncwarp();
            int mcnt = min(16, mdeg - base);
            for (int it = 0; it < mcnt; it++) {
                int se = __shfl_sync(FULL, s, half * 16 + it);
                if (it < cnt) {
                    float w = swp[it * 4 + head];
                    float4 h2 = *(const float4*)&g_h[se * 64 + j * 4];
                    acc.x += w * h2.x; acc.y += w * h2.y;
                    acc.z += w * h2.z; acc.w += w * h2.w;
                }
            }
            __syncwarp();
        }

        // reduce den4 across the 16 lanes of this half (xor<=8 stays in half)
#pragma unroll
        for (int off = 8; off >= 1; off >>= 1) {
            den4.x += __shfl_xor_sync(FULL, den4.x, off);
            den4.y += __shfl_xor_sync(FULL, den4.y, off);
            den4.z += __shfl_xor_sync(FULL, den4.z, off);
            den4.w += __shfl_xor_sync(FULL, den4.w, off);
        }
        float den = (head == 0) ? den4.x : (head == 1) ? den4.y
                  : (head == 2) ? den4.z : den4.w;
        float inv = 1.f / (den + 1e-16f);
        float4 bv = *(const float4*)&bias[j * 4];
        float4 v;
        v.x = acc.x * inv + bv.x; v.y = acc.y * inv + bv.y;
        v.z = acc.z * inv + bv.z; v.w = acc.w * inv + bv.w;
        if (ELU) {
            v.x = v.x > 0.f ? v.x : (__expf(v.x) - 1.f);
            v.y = v.y > 0.f ? v.y : (__expf(v.y) - 1.f);
            v.z = v.z > 0.f ? v.z : (__expf(v.z) - 1.f);
            v.w = v.w > 0.f ? v.w : (__expf(v.w) - 1.f);
        }
        *(float4*)&out[d * 64 + j * 4] = v;
    } else {
        float adv = g_ad[d];
        float ws  = __expf(lrelu(g_as[d] + adv));
        float den = (j == 0) ? ws : 0.f;

        float4 hv = *(const float4*)&g_h[d * 64 + j * 4];
        acc.x = ws * hv.x; acc.y = ws * hv.y;
        acc.z = ws * hv.z; acc.w = ws * hv.w;

        for (int base = 0; base < mdeg; base += 16) {
            int cnt  = deg - base;
            int s = 0;
            if (j < cnt) {
                s = g_csrc[start + base + j];
                float w = __expf(lrelu(g_as[s] + adv));
                den += w;
                swp[j] = w;
            }
            __syncwarp();
            int mcnt = min(16, mdeg - base);
            for (int it = 0; it < mcnt; it++) {
                int se = __shfl_sync(FULL, s, half * 16 + it);
                if (it < cnt) {
                    float w = swp[it];
                    float4 h2 = *(const float4*)&g_h[se * 64 + j * 4];
                    acc.x += w * h2.x; acc.y += w * h2.y;
                    acc.z += w * h2.z; acc.w += w * h2.w;
                }
            }
            __syncwarp();
        }

#pragma unroll
        for (int off = 8; off >= 1; off >>= 1)
            den += __shfl_xor_sync(FULL, den, off);
        float inv = 1.f / (den + 1e-16f);
        float4 bv = *(const float4*)&bias[j * 4];
        float4 v;
        v.x = acc.x * inv + bv.x; v.y = acc.y * inv + bv.y;
        v.z = acc.z * inv + bv.z; v.w = acc.w * inv + bv.w;
        *(float4*)&out[d * 64 + j * 4] = v;
    }
}

// ---------------- launch -------------------------------------------------------
extern "C" void kernel_launch(void* const* d_in, const int* in_sizes, int n_in,
                              void* d_out, int out_size) {
    const float* x   = (const float*)d_in[0];
    const int*   ei  = (const int*)d_in[1];
    const float* W0  = (const float*)d_in[2];
    const float* as0 = (const float*)d_in[3];
    const float* ad0 = (const float*)d_in[4];
    const float* b0  = (const float*)d_in[5];
    const float* W1  = (const float*)d_in[6];
    const float* as1 = (const float*)d_in[7];
    const float* ad1 = (const float*)d_in[8];
    const float* b1  = (const float*)d_in[9];
    const float* W2  = (const float*)d_in[10];
    const float* as2 = (const float*)d_in[11];
    const float* ad2 = (const float*)d_in[12];
    const float* b2  = (const float*)d_in[13];
    float* out = (float*)d_out;

    float *featA, *featB;
    cudaGetSymbolAddress((void**)&featA, g_featA);
    cudaGetSymbolAddress((void**)&featB, g_featB);

    const int smem128 = (64 * 64 + 64 * 132) * 4;   // 50176 B
    const int smem64  = (64 * 64 + 64 * 68) * 4;    // 33792 B
    cudaFuncSetAttribute(gemm_alpha_kernel<128, 4, true>,
                         cudaFuncAttributeMaxDynamicSharedMemorySize, smem128);
    cudaFuncSetAttribute(gemm_alpha_kernel<64, 4, false>,
                         cudaFuncAttributeMaxDynamicSharedMemorySize, smem64);
    cudaFuncSetAttribute(gemm_alpha_kernel<64, 1, false>,
                         cudaFuncAttributeMaxDynamicSharedMemorySize, smem64);

    const int gemm_grid = (NN + 63) / 64;            // 782
    const int hist_grid = (EE / 4 + 255) / 256;      // 782 (4 edges/thread)
    const int edge_grid = (EE + 255) / 256;          // 3125
    const int gath_grid = (NN / 2 * 32 + 255) / 256; // 2 nodes/warp -> 3125

    // K1: layer-0 GEMM ⊕ edge histogram (independent work, heterogeneous blocks)
    gemm_alpha_kernel<128, 4, true>
        <<<gemm_grid + hist_grid, 256, smem128>>>(x, W0, as0, ad0, ei, gemm_grid);
    scan_kernel<<<1, 1024>>>();                      // K2
    scatter_kernel<<<edge_grid, 256>>>(ei);          // K3 (also re-zeroes g_deg)
    gather_kernel<4, true><<<gath_grid, 256>>>(b0, featA);   // K4 -> profiled

    // layer 1 : 64 -> 4x16, ELU
    gemm_alpha_kernel<64, 4, false>
        <<<gemm_grid, 256, smem64>>>(featA, W1, as1, ad1, ei, gemm_grid);
    gather_kernel<4, true><<<gath_grid, 256>>>(b1, featB);

    // layer 2 : 64 -> 1x64, no ELU
    gemm_alpha_kernel<64, 1, false>
        <<<gemm_grid, 256, smem64>>>(featB, W2, as2, ad2, ei, gemm_grid);
    gather_kernel<1, false><<<gath_grid, 256>>>(b2, out);
}